// round 1
// baseline (speedup 1.0000x reference)
#include <cuda_runtime.h>
#include <cstdint>

#define B_    256
#define L_    8192
#define DIM_  256
#define NPAT  64
#define HIST  32
#define WIN   8
#define T_    1024
#define TCHUNK 128

// Static scratch (no allocations allowed).
__device__ float g_scores[(size_t)B_ * T_ * NPAT];   // 64 MB, layout [b][t][p]
__device__ float g_W[HIST * NPAT];                   // folded conv_w^T @ keys_w^T, [h][p]
__device__ float g_b2[NPAT];                         // keys_w @ conv_b
__device__ float g_avg0[B_ * NPAT];                  // centered avg_init

// ---------------------------------------------------------------------------
// Setup 1: fold W[h][p] = sum_d conv_w[d,0,h]*keys_w[p,d]  (fp64 accumulate)
//          b2[p]  = sum_d conv_b[d]*keys_w[p,d]
// grid 64 x 32 threads -> 2048 threads, one (h,p) each.
// ---------------------------------------------------------------------------
__global__ void fold_kernel(const float* __restrict__ conv_w,
                            const float* __restrict__ conv_b,
                            const float* __restrict__ keys_w) {
    int id = blockIdx.x * 32 + threadIdx.x;
    int p = id & (NPAT - 1);
    int h = id >> 6;
    double acc = 0.0;
    for (int d = 0; d < DIM_; d++)
        acc += (double)conv_w[d * HIST + h] * (double)keys_w[p * DIM_ + d];
    g_W[h * NPAT + p] = (float)acc;
    if (h == 0) {
        double ab = 0.0;
        for (int d = 0; d < DIM_; d++)
            ab += (double)conv_b[d] * (double)keys_w[p * DIM_ + d];
        g_b2[p] = (float)ab;
    }
}

// ---------------------------------------------------------------------------
// Setup 2: avg0[b][p] = avg_init[b][p] - mean_p(avg_init[b])
// grid B_ x 64 threads
// ---------------------------------------------------------------------------
__global__ void avg_kernel(const float* __restrict__ avg_init) {
    int b = blockIdx.x, p = threadIdx.x;
    __shared__ double s[NPAT];
    float v = avg_init[b * NPAT + p];
    s[p] = (double)v;
    __syncthreads();
    for (int o = 32; o > 0; o >>= 1) {
        if (p < o) s[p] += s[p + o];
        __syncthreads();
    }
    float mean = (float)(s[0] * (1.0 / 64.0));
    g_avg0[b * NPAT + p] = v - mean;
}

// ---------------------------------------------------------------------------
// Scores: scores[b][t][p] = clip(b2[p] + sum_h x[b, t*8-31+h] * W[h][p], 0, 6)
// grid (8 chunks, 256 batches) x 256 threads. x window staged in smem,
// W column cached in registers, float4 smem loads (broadcast across 64 threads).
// ---------------------------------------------------------------------------
__global__ void scores_kernel(const float* __restrict__ x) {
    int tc = blockIdx.x, b = blockIdx.y;
    int t0 = tc * TCHUNK;
    __shared__ __align__(16) float xs[TCHUNK * WIN + HIST - WIN]; // 1048 floats
    const int XN = TCHUNK * WIN + HIST - WIN;
    int base = t0 * WIN - (HIST - 1);
    for (int i = threadIdx.x; i < XN; i += blockDim.x) {
        int g = base + i;
        xs[i] = (g >= 0) ? x[(size_t)b * L_ + g] : 0.0f;
    }
    int p  = threadIdx.x & (NPAT - 1);
    int tg = threadIdx.x >> 6;          // 0..3
    float w[HIST];
#pragma unroll
    for (int h = 0; h < HIST; h++) w[h] = g_W[h * NPAT + p];
    float bias = g_b2[p];
    __syncthreads();
    const float4* xs4 = (const float4*)xs;
    for (int tl = tg; tl < TCHUNK; tl += 4) {
        int o4 = tl * 2;                 // (tl*8)/4
        float acc = bias;
#pragma unroll
        for (int j = 0; j < 8; j++) {
            float4 v = xs4[o4 + j];
            acc = fmaf(v.x, w[4 * j + 0], acc);
            acc = fmaf(v.y, w[4 * j + 1], acc);
            acc = fmaf(v.z, w[4 * j + 2], acc);
            acc = fmaf(v.w, w[4 * j + 3], acc);
        }
        acc = fminf(fmaxf(acc, 0.0f), 6.0f);
        g_scores[((size_t)b * T_ + (t0 + tl)) * NPAT + p] = acc;
    }
}

// Order-preserving float->uint map (finite values; monotonic).
__device__ __forceinline__ unsigned okey(float f) {
    unsigned u = __float_as_uint(f);
    return u ^ (unsigned)(((int)u >> 31) | (int)0x80000000);
}

// ---------------------------------------------------------------------------
// Scan + decode: one warp per batch. Lane L owns patterns L and L+32.
// Exact replication of reference: idx = first-argmax(score - avg);
// avg = (avg + onehot) - 1/64 with identical fp rounding.
// Then out[b][t*8+w] = relu(shapes[w][idx[t]] - x[b][t*8+w]).
// grid 256 x 32 threads.
// ---------------------------------------------------------------------------
__global__ void scan_kernel(const float* __restrict__ x,
                            const float* __restrict__ shapes_w,
                            float* __restrict__ out) {
    int b = blockIdx.x;
    int lane = threadIdx.x;              // 0..31
    __shared__ int idx_s[T_];
    __shared__ float shp[NPAT][WIN];     // transposed: [p][w]
    for (int i = lane; i < NPAT * WIN; i += 32) {
        int pp = i >> 3, ww = i & 7;
        shp[pp][ww] = shapes_w[ww * NPAT + pp];
    }
    float a0 = g_avg0[b * NPAT + lane];
    float a1 = g_avg0[b * NPAT + 32 + lane];
    const float* sb = g_scores + (size_t)b * T_ * NPAT;

    // 4-deep score prefetch ring (loads independent of scan state).
    float s0[4], s1[4];
#pragma unroll
    for (int j = 0; j < 4; j++) {
        s0[j] = sb[j * NPAT + lane];
        s1[j] = sb[j * NPAT + 32 + lane];
    }

#pragma unroll 4
    for (int t = 0; t < T_; t++) {
        int slot = t & 3;
        float d0 = s0[slot] - a0;
        float d1 = s1[slot] - a1;
        int tp = t + 4;
        if (tp < T_) {
            s0[slot] = sb[tp * NPAT + lane];
            s1[slot] = sb[tp * NPAT + 32 + lane];
        }
        unsigned k0 = okey(d0), k1 = okey(d1);
        unsigned kb; int cb;
        if (k1 > k0) { kb = k1; cb = lane + 32; }   // tie -> lower index
        else         { kb = k0; cb = lane; }
        unsigned m = __reduce_max_sync(0xffffffffu, kb);
        unsigned cand = (kb == m) ? (unsigned)cb : 64u;
        int c = (int)__reduce_min_sync(0xffffffffu, cand);  // first-max index
        if (lane == 0) idx_s[t] = c;
        // exact: (avg + prob) - 1/64, both roundings preserved
        a0 = (a0 + ((c == lane)      ? 1.0f : 0.0f)) - 0.015625f;
        a1 = (a1 + ((c == lane + 32) ? 1.0f : 0.0f)) - 0.015625f;
    }
    __syncwarp();

    const float* xb = x + (size_t)b * L_;
    float* ob = out + (size_t)b * L_;
#pragma unroll 8
    for (int i = lane; i < L_; i += 32) {
        int t = i >> 3, ww = i & 7;
        int c = idx_s[t];
        ob[i] = fmaxf(shp[c][ww] - xb[i], 0.0f);
    }
}

extern "C" void kernel_launch(void* const* d_in, const int* in_sizes, int n_in,
                              void* d_out, int out_size) {
    const float* x        = (const float*)d_in[0];
    const float* avg_init = (const float*)d_in[1];
    const float* conv_w   = (const float*)d_in[2];
    const float* conv_b   = (const float*)d_in[3];
    const float* keys_w   = (const float*)d_in[4];
    const float* shapes_w = (const float*)d_in[5];
    float* out = (float*)d_out;

    fold_kernel<<<64, 32>>>(conv_w, conv_b, keys_w);
    avg_kernel<<<B_, 64>>>(avg_init);
    scores_kernel<<<dim3(8, B_), 256>>>(x);
    scan_kernel<<<B_, 32>>>(x, shapes_w, out);
}